// round 2
// baseline (speedup 1.0000x reference)
#include <cuda_runtime.h>
#include <math.h>

#define LL 256
#define DD 128
#define NHEAD 4
#define DHEAD 32
#define NROWS (LL*LL)   // 65536

// ---------------- scratch (device globals; no allocation allowed) ----------------
__device__ float g_WT[5][DD*DD];                 // Wq,Wk,Wv,Wg,Wo transposed: [d][e]
__device__ float g_q[(size_t)NROWS*DD];
__device__ float g_k[(size_t)NROWS*DD];
__device__ float g_v[(size_t)NROWS*DD];
__device__ float g_gate[(size_t)NROWS*DD];
__device__ float g_att[(size_t)NROWS*DD];
__device__ unsigned g_mask[LL*8];                // packed mask bits: row j, 8 words of 32

// ---------------- kernel 0: transpose weights ----------------
__global__ void k_transpose(const float* __restrict__ Wq, const float* __restrict__ Wk,
                            const float* __restrict__ Wv, const float* __restrict__ Wg,
                            const float* __restrict__ Wo)
{
    int m = blockIdx.x;
    const float* W = (m==0)?Wq:(m==1)?Wk:(m==2)?Wv:(m==3)?Wg:Wo;
    float* dst = g_WT[m];
    for (int idx = threadIdx.x; idx < DD*DD; idx += blockDim.x) {
        int d = idx & 127;      // fast-varying -> coalesced read
        int e = idx >> 7;
        dst[d*DD + e] = W[e*DD + d];
    }
}

// ---------------- kernel 0b: pack mask ----------------
// mask arrives as a 4-byte dtype (bool -> int32 or float32 by the harness).
// Nonzero-bits test is correct for both.
__global__ void k_maskpack(const int* __restrict__ mask)
{
    int j = threadIdx.x;              // 0..255
    const int* mrow = mask + (size_t)j*LL;
    #pragma unroll
    for (int w = 0; w < 8; w++) {
        unsigned bits = 0;
        #pragma unroll
        for (int b = 0; b < 32; b++) bits |= (mrow[w*32+b] != 0 ? 1u : 0u) << b;
        g_mask[j*8 + w] = bits;
    }
}

// ---------------- kernel 1: LayerNorm + q/k/v/gate projections ----------------
// block: 128 threads, 64 rows. smem: pn[64][132] + Ws[128][128]
#define PN_STRIDE 132
__global__ __launch_bounds__(128) void k_lnproj(
    const float* __restrict__ pair,
    const float* __restrict__ ln_g, const float* __restrict__ ln_b,
    const float* __restrict__ bq, const float* __restrict__ bk,
    const float* __restrict__ bv, const float* __restrict__ bg)
{
    extern __shared__ float sm[];
    float* pn = sm;                       // 64*132 floats
    float* Ws = sm + 64*PN_STRIDE;        // 128*128 floats
    const int row0 = blockIdx.x * 64;
    const int tid  = threadIdx.x;
    const int lane = tid & 31, warp = tid >> 5;

    // ---- LayerNorm: warp handles 16 rows ----
    float lg0 = ln_g[lane],    lg1 = ln_g[lane+32], lg2 = ln_g[lane+64], lg3 = ln_g[lane+96];
    float lb0 = ln_b[lane],    lb1 = ln_b[lane+32], lb2 = ln_b[lane+64], lb3 = ln_b[lane+96];
    for (int rr = 0; rr < 16; rr++) {
        int r = warp*16 + rr;
        const float* x = pair + (size_t)(row0 + r)*DD;
        float v0 = x[lane], v1 = x[lane+32], v2 = x[lane+64], v3 = x[lane+96];
        float s = v0+v1+v2+v3;
        #pragma unroll
        for (int o = 16; o > 0; o >>= 1) s += __shfl_xor_sync(0xffffffffu, s, o);
        float mu = s * (1.f/128.f);
        float d0 = v0-mu, d1 = v1-mu, d2 = v2-mu, d3 = v3-mu;
        float sq = d0*d0 + d1*d1 + d2*d2 + d3*d3;
        #pragma unroll
        for (int o = 16; o > 0; o >>= 1) sq += __shfl_xor_sync(0xffffffffu, sq, o);
        float rstd = rsqrtf(sq*(1.f/128.f) + 1e-5f);
        float* p = pn + r*PN_STRIDE;
        p[lane]    = d0*rstd*lg0 + lb0;
        p[lane+32] = d1*rstd*lg1 + lb1;
        p[lane+64] = d2*rstd*lg2 + lb2;
        p[lane+96] = d3*rstd*lg3 + lb3;
    }
    __syncthreads();

    const int rt = tid >> 4;   // 0..7  -> rows rt*8..rt*8+7
    const int ct = tid & 15;   // 0..15 -> cols ct*8..ct*8+7
    const float4* pn4 = (const float4*)pn;
    float4* Ws4 = (float4*)Ws;

    for (int p = 0; p < 4; p++) {
        // load transposed weights into smem
        const float4* Wsrc = (const float4*)(g_WT[p]);
        for (int idx = tid; idx < (DD*DD)/4; idx += 128) Ws4[idx] = Wsrc[idx];
        __syncthreads();

        float acc[8][8];
        #pragma unroll
        for (int ii = 0; ii < 8; ii++)
            #pragma unroll
            for (int jj = 0; jj < 8; jj++) acc[ii][jj] = 0.f;

        #pragma unroll 2
        for (int d4 = 0; d4 < 32; d4++) {
            float4 a[8];
            #pragma unroll
            for (int ii = 0; ii < 8; ii++)
                a[ii] = pn4[(rt*8+ii)*(PN_STRIDE/4) + d4];
            #pragma unroll
            for (int l = 0; l < 4; l++) {
                float4 b0 = Ws4[(d4*4+l)*32 + ct*2];
                float4 b1 = Ws4[(d4*4+l)*32 + ct*2 + 1];
                #pragma unroll
                for (int ii = 0; ii < 8; ii++) {
                    float av = (l==0)?a[ii].x:(l==1)?a[ii].y:(l==2)?a[ii].z:a[ii].w;
                    acc[ii][0] += av*b0.x; acc[ii][1] += av*b0.y;
                    acc[ii][2] += av*b0.z; acc[ii][3] += av*b0.w;
                    acc[ii][4] += av*b1.x; acc[ii][5] += av*b1.y;
                    acc[ii][6] += av*b1.z; acc[ii][7] += av*b1.w;
                }
            }
        }

        const float* bias = (p==0)?bq:(p==1)?bk:(p==2)?bv:bg;
        float* dst = (p==0)?g_q:(p==1)?g_k:(p==2)?g_v:g_gate;
        float bb[8];
        #pragma unroll
        for (int jj = 0; jj < 8; jj++) bb[jj] = bias[ct*8+jj];
        #pragma unroll
        for (int ii = 0; ii < 8; ii++) {
            size_t rbase = (size_t)(row0 + rt*8 + ii)*DD + ct*8;
            float vo[8];
            #pragma unroll
            for (int jj = 0; jj < 8; jj++) {
                float val = acc[ii][jj] + bb[jj];
                if (p == 3) val = 1.f/(1.f + __expf(-val));
                vo[jj] = val;
            }
            *(float4*)(dst + rbase)     = make_float4(vo[0],vo[1],vo[2],vo[3]);
            *(float4*)(dst + rbase + 4) = make_float4(vo[4],vo[5],vo[6],vo[7]);
        }
        __syncthreads();   // before next projection overwrites Ws
    }
}

// ---------------- kernel 2: attention per (i,h) ----------------
// block: 256 threads (thread j = query row), smem q[256][36], k[256][32], v[256][32]
__global__ __launch_bounds__(256) void k_attn()
{
    extern __shared__ float sm[];
    float* qs = sm;                  // stride 36 (reg-load, avoid conflicts)
    float* ks = sm + 256*36;         // stride 32 (broadcast reads)
    float* vs = ks + 256*32;
    const int i = blockIdx.x, h = blockIdx.y;
    const int tid = threadIdx.x;
    const size_t base = ((size_t)i*LL)*DD + h*DHEAD;

    for (int idx = tid; idx < 2048; idx += 256) {  // 256 rows * 8 float4
        int r = idx >> 3, c = idx & 7;
        size_t g = base + (size_t)r*DD + c*4;
        ((float4*)qs)[r*9 + c] = *(const float4*)(g_q + g);
        ((float4*)ks)[r*8 + c] = *(const float4*)(g_k + g);
        ((float4*)vs)[r*8 + c] = *(const float4*)(g_v + g);
    }
    __syncthreads();

    const int j = tid;
    float q[32];
    #pragma unroll
    for (int d4 = 0; d4 < 8; d4++) {
        float4 t = ((const float4*)qs)[j*9 + d4];
        q[4*d4] = t.x; q[4*d4+1] = t.y; q[4*d4+2] = t.z; q[4*d4+3] = t.w;
    }
    // packed mask row (mask indexed [j,k], independent of i,h)
    unsigned mw[8];
    #pragma unroll
    for (int w = 0; w < 8; w++) mw[w] = g_mask[j*8 + w];

    float m = -1e30f, lsum = 0.f, o[32];
    #pragma unroll
    for (int d = 0; d < 32; d++) o[d] = 0.f;
    const float scale = 0.17677669529663687f;   // 1/sqrt(32)

    for (int k = 0; k < 256; k++) {
        float s = 0.f;
        #pragma unroll
        for (int d4 = 0; d4 < 8; d4++) {
            float4 kk = ((const float4*)ks)[k*8 + d4];
            s += q[4*d4]*kk.x + q[4*d4+1]*kk.y + q[4*d4+2]*kk.z + q[4*d4+3]*kk.w;
        }
        s *= scale;
        bool valid = (mw[k >> 5] >> (k & 31)) & 1u;
        s = valid ? s : -1e9f;
        if (s > m) {
            float corr = __expf(m - s);
            lsum *= corr;
            #pragma unroll
            for (int d = 0; d < 32; d++) o[d] *= corr;
            m = s;
        }
        float e = __expf(s - m);
        lsum += e;
        #pragma unroll
        for (int d4 = 0; d4 < 8; d4++) {
            float4 vv = ((const float4*)vs)[k*8 + d4];
            o[4*d4]   += e*vv.x; o[4*d4+1] += e*vv.y;
            o[4*d4+2] += e*vv.z; o[4*d4+3] += e*vv.w;
        }
    }
    float inv = 1.f / lsum;
    __syncthreads();  // done reading qs
    #pragma unroll
    for (int d = 0; d < 32; d++) qs[j*36 + d] = o[d]*inv;
    __syncthreads();
    for (int idx = tid; idx < 2048; idx += 256) {
        int r = idx >> 3, c = idx & 7;
        *(float4*)(g_att + base + (size_t)r*DD + c*4) = ((const float4*)qs)[r*9 + c];
    }
}

// ---------------- kernel 3: out projection + gate ----------------
__global__ __launch_bounds__(128) void k_outproj(const float* __restrict__ bo,
                                                 float* __restrict__ out)
{
    extern __shared__ float sm[];
    float* As = sm;                    // [64][132]
    float* Ws = sm + 64*PN_STRIDE;     // [128][128]
    const int row0 = blockIdx.x * 64;
    const int tid  = threadIdx.x;

    for (int idx = tid; idx < 2048; idx += 128) {   // 64 rows * 32 float4
        int r = idx >> 5, c = idx & 31;
        ((float4*)As)[r*(PN_STRIDE/4) + c] = *(const float4*)(g_att + (size_t)(row0+r)*DD + c*4);
    }
    const float4* Wsrc = (const float4*)(g_WT[4]);
    float4* Ws4 = (float4*)Ws;
    for (int idx = tid; idx < (DD*DD)/4; idx += 128) Ws4[idx] = Wsrc[idx];
    __syncthreads();

    const int rt = tid >> 4, ct = tid & 15;
    const float4* A4 = (const float4*)As;

    float acc[8][8];
    #pragma unroll
    for (int ii = 0; ii < 8; ii++)
        #pragma unroll
        for (int jj = 0; jj < 8; jj++) acc[ii][jj] = 0.f;

    #pragma unroll 2
    for (int d4 = 0; d4 < 32; d4++) {
        float4 a[8];
        #pragma unroll
        for (int ii = 0; ii < 8; ii++)
            a[ii] = A4[(rt*8+ii)*(PN_STRIDE/4) + d4];
        #pragma unroll
        for (int l = 0; l < 4; l++) {
            float4 b0 = Ws4[(d4*4+l)*32 + ct*2];
            float4 b1 = Ws4[(d4*4+l)*32 + ct*2 + 1];
            #pragma unroll
            for (int ii = 0; ii < 8; ii++) {
                float av = (l==0)?a[ii].x:(l==1)?a[ii].y:(l==2)?a[ii].z:a[ii].w;
                acc[ii][0] += av*b0.x; acc[ii][1] += av*b0.y;
                acc[ii][2] += av*b0.z; acc[ii][3] += av*b0.w;
                acc[ii][4] += av*b1.x; acc[ii][5] += av*b1.y;
                acc[ii][6] += av*b1.z; acc[ii][7] += av*b1.w;
            }
        }
    }

    float bb[8];
    #pragma unroll
    for (int jj = 0; jj < 8; jj++) bb[jj] = bo[ct*8+jj];
    #pragma unroll
    for (int ii = 0; ii < 8; ii++) {
        size_t rbase = (size_t)(row0 + rt*8 + ii)*DD + ct*8;
        float4 gt0 = *(const float4*)(g_gate + rbase);
        float4 gt1 = *(const float4*)(g_gate + rbase + 4);
        float4 o0, o1;
        o0.x = (acc[ii][0]+bb[0])*gt0.x; o0.y = (acc[ii][1]+bb[1])*gt0.y;
        o0.z = (acc[ii][2]+bb[2])*gt0.z; o0.w = (acc[ii][3]+bb[3])*gt0.w;
        o1.x = (acc[ii][4]+bb[4])*gt1.x; o1.y = (acc[ii][5]+bb[5])*gt1.y;
        o1.z = (acc[ii][6]+bb[6])*gt1.z; o1.w = (acc[ii][7]+bb[7])*gt1.w;
        *(float4*)(out + rbase)     = o0;
        *(float4*)(out + rbase + 4) = o1;
    }
}

// ---------------- launch ----------------
extern "C" void kernel_launch(void* const* d_in, const int* in_sizes, int n_in,
                              void* d_out, int out_size)
{
    const float* pair = (const float*)d_in[0];
    const int*   mask = (const int*)d_in[1];
    const float* ln_g = (const float*)d_in[2];
    const float* ln_b = (const float*)d_in[3];
    const float* Wq = (const float*)d_in[4];  const float* bq = (const float*)d_in[5];
    const float* Wk = (const float*)d_in[6];  const float* bk = (const float*)d_in[7];
    const float* Wv = (const float*)d_in[8];  const float* bv = (const float*)d_in[9];
    const float* Wo = (const float*)d_in[10]; const float* bo = (const float*)d_in[11];
    const float* Wg = (const float*)d_in[12]; const float* bg = (const float*)d_in[13];
    float* out = (float*)d_out;

    const int smemP = (64*PN_STRIDE + DD*DD) * 4;            // ~99 KB
    const int smemA = (256*36 + 2*256*32) * 4;               // ~102 KB
    cudaFuncSetAttribute(k_lnproj,  cudaFuncAttributeMaxDynamicSharedMemorySize, smemP);
    cudaFuncSetAttribute(k_outproj, cudaFuncAttributeMaxDynamicSharedMemorySize, smemP);
    cudaFuncSetAttribute(k_attn,    cudaFuncAttributeMaxDynamicSharedMemorySize, smemA);

    k_transpose<<<5, 256>>>(Wq, Wk, Wv, Wg, Wo);
    k_maskpack<<<1, 256>>>(mask);
    k_lnproj<<<NROWS/64, 128, smemP>>>(pair, ln_g, ln_b, bq, bk, bv, bg);
    dim3 ga(LL, NHEAD);
    k_attn<<<ga, 256, smemA>>>();
    k_outproj<<<NROWS/64, 128, smemP>>>(bo, out);
}

// round 4
// speedup vs baseline: 2.1419x; 2.1419x over previous
#include <cuda_runtime.h>
#include <cuda_bf16.h>
#include <cstdint>
#include <math.h>

#define LL 256
#define DD 128
#define NHEAD 4
#define DHEAD 32
#define NROWS (LL*LL)   // 65536
#define WST 68          // packed-pair row stride (uint32) for 128-wide matrices

// ---------------- scratch ----------------
__device__ uint32_t g_WbH[5*128*WST];   // bf16-hi packed pairs, rows=e, pairs along d
__device__ uint32_t g_WbL[5*128*WST];   // bf16-lo
__device__ float g_q[(size_t)NROWS*DD];
__device__ float g_k[(size_t)NROWS*DD];
__device__ float g_v[(size_t)NROWS*DD];
__device__ float g_gate[(size_t)NROWS*DD];
__device__ float g_att[(size_t)NROWS*DD];
__device__ unsigned g_mask[LL*8];

// ---------------- helpers ----------------
__device__ __forceinline__ uint32_t pack_bf16(__nv_bfloat16 a, __nv_bfloat16 b){
    __nv_bfloat162 t; t.x = a; t.y = b;
    return *reinterpret_cast<uint32_t*>(&t);
}
__device__ __forceinline__ void split2(float x0, float x1, uint32_t& hi, uint32_t& lo){
    __nv_bfloat16 h0 = __float2bfloat16(x0);
    __nv_bfloat16 h1 = __float2bfloat16(x1);
    __nv_bfloat16 l0 = __float2bfloat16(x0 - __bfloat162float(h0));
    __nv_bfloat16 l1 = __float2bfloat16(x1 - __bfloat162float(h1));
    hi = pack_bf16(h0, h1); lo = pack_bf16(l0, l1);
}
__device__ __forceinline__ void split1(float x, __nv_bfloat16& h, __nv_bfloat16& l){
    h = __float2bfloat16(x);
    l = __float2bfloat16(x - __bfloat162float(h));
}
__device__ __forceinline__ void mma16816(float* c, const uint32_t* a, uint32_t b0, uint32_t b1){
    asm volatile("mma.sync.aligned.m16n8k16.row.col.f32.bf16.bf16.f32 "
        "{%0,%1,%2,%3}, {%4,%5,%6,%7}, {%8,%9}, {%0,%1,%2,%3};\n"
        : "+f"(c[0]), "+f"(c[1]), "+f"(c[2]), "+f"(c[3])
        : "r"(a[0]), "r"(a[1]), "r"(a[2]), "r"(a[3]), "r"(b0), "r"(b1));
}

// ---------------- kernel: prep weights (split + pack pairs along d) ----------------
__global__ void k_prep(const float* __restrict__ Wq, const float* __restrict__ Wk,
                       const float* __restrict__ Wv, const float* __restrict__ Wg,
                       const float* __restrict__ Wo)
{
    int m = blockIdx.x;
    const float* W = (m==0)?Wq:(m==1)?Wk:(m==2)?Wv:(m==3)?Wg:Wo;
    uint32_t* H = g_WbH + m*128*WST;
    uint32_t* L = g_WbL + m*128*WST;
    for (int idx = threadIdx.x; idx < 128*WST; idx += blockDim.x){
        int e = idx / WST, p = idx % WST;
        uint32_t hv = 0, lv = 0;
        if (p < 64){
            float x0 = W[e*DD + 2*p], x1 = W[e*DD + 2*p + 1];
            split2(x0, x1, hv, lv);
        }
        H[idx] = hv; L[idx] = lv;
    }
}

// ---------------- kernel: pack mask ----------------
__global__ void k_maskpack(const int* __restrict__ mask)
{
    int j = threadIdx.x;
    const int* mrow = mask + (size_t)j*LL;
    #pragma unroll
    for (int w = 0; w < 8; w++){
        unsigned bits = 0;
        #pragma unroll
        for (int b = 0; b < 32; b++) bits |= (mrow[w*32+b] != 0 ? 1u : 0u) << b;
        g_mask[j*8 + w] = bits;
    }
}

// ---------------- kernel 1: LayerNorm + q/k/v/gate projections (tensor) ----------------
// 256 threads, 64 rows/block. smem: PN hi/lo [64][68] + W hi/lo [128][68] = 104.4KB
__global__ __launch_bounds__(256,2) void k_lnproj(
    const float* __restrict__ pair,
    const float* __restrict__ ln_g, const float* __restrict__ ln_b,
    const float* __restrict__ bq, const float* __restrict__ bk,
    const float* __restrict__ bv, const float* __restrict__ bg)
{
    extern __shared__ uint32_t sm[];
    uint32_t* PNH = sm;                 // 64*68
    uint32_t* PNL = sm + 64*WST;
    uint32_t* WH  = sm + 2*64*WST;      // 128*68
    uint32_t* WL  = WH + 128*WST;
    __nv_bfloat16* PNHh = (__nv_bfloat16*)PNH;
    __nv_bfloat16* PNLh = (__nv_bfloat16*)PNL;

    const int row0 = blockIdx.x * 64;
    const int tid = threadIdx.x;
    const int lane = tid & 31, wid = tid >> 5;
    const int gid = lane >> 2, tig = lane & 3;

    // ---- LayerNorm: 8 warps x 8 rows, split to bf16 hi/lo in smem ----
    float lg[4], lb[4];
    #pragma unroll
    for (int t = 0; t < 4; t++){ lg[t] = ln_g[lane + 32*t]; lb[t] = ln_b[lane + 32*t]; }
    for (int rr = 0; rr < 8; rr++){
        int r = wid*8 + rr;
        const float* x = pair + (size_t)(row0 + r)*DD;
        float v[4];
        #pragma unroll
        for (int t = 0; t < 4; t++) v[t] = x[lane + 32*t];
        float s = v[0]+v[1]+v[2]+v[3];
        #pragma unroll
        for (int o = 16; o > 0; o >>= 1) s += __shfl_xor_sync(0xffffffffu, s, o);
        float mu = s * (1.f/128.f);
        float sq = 0.f;
        #pragma unroll
        for (int t = 0; t < 4; t++){ v[t] -= mu; sq += v[t]*v[t]; }
        #pragma unroll
        for (int o = 16; o > 0; o >>= 1) sq += __shfl_xor_sync(0xffffffffu, sq, o);
        float rstd = rsqrtf(sq*(1.f/128.f) + 1e-5f);
        #pragma unroll
        for (int t = 0; t < 4; t++){
            float pn = v[t]*rstd*lg[t] + lb[t];
            __nv_bfloat16 h, l; split1(pn, h, l);
            PNHh[r*(2*WST) + lane + 32*t] = h;
            PNLh[r*(2*WST) + lane + 32*t] = l;
        }
    }
    __syncthreads();

    const int wm = wid >> 2, wn = wid & 3;
    const int m0 = wm*32, n0 = wn*32;

    for (int p = 0; p < 4; p++){
        // stage weights
        const float4* sH = (const float4*)(g_WbH + p*128*WST);
        const float4* sL = (const float4*)(g_WbL + p*128*WST);
        float4* dH = (float4*)WH; float4* dL = (float4*)WL;
        for (int idx = tid; idx < 128*WST/4; idx += 256){ dH[idx] = sH[idx]; dL[idx] = sL[idx]; }
        __syncthreads();

        float C[2][4][4];
        #pragma unroll
        for (int mi=0; mi<2; mi++)
            #pragma unroll
            for (int nf=0; nf<4; nf++)
                #pragma unroll
                for (int q=0; q<4; q++) C[mi][nf][q] = 0.f;

        #pragma unroll
        for (int ks = 0; ks < 8; ks++){
            uint32_t AH[2][4], AL[2][4];
            #pragma unroll
            for (int mi = 0; mi < 2; mi++){
                int r = m0 + mi*16 + gid;
                AH[mi][0] = PNH[r*WST + ks*8 + tig];
                AH[mi][1] = PNH[(r+8)*WST + ks*8 + tig];
                AH[mi][2] = PNH[r*WST + ks*8 + tig + 4];
                AH[mi][3] = PNH[(r+8)*WST + ks*8 + tig + 4];
                AL[mi][0] = PNL[r*WST + ks*8 + tig];
                AL[mi][1] = PNL[(r+8)*WST + ks*8 + tig];
                AL[mi][2] = PNL[r*WST + ks*8 + tig + 4];
                AL[mi][3] = PNL[(r+8)*WST + ks*8 + tig + 4];
            }
            #pragma unroll
            for (int nf = 0; nf < 4; nf++){
                int e = n0 + nf*8 + gid;
                uint32_t bh0 = WH[e*WST + ks*8 + tig];
                uint32_t bh1 = WH[e*WST + ks*8 + tig + 4];
                uint32_t bl0 = WL[e*WST + ks*8 + tig];
                uint32_t bl1 = WL[e*WST + ks*8 + tig + 4];
                #pragma unroll
                for (int mi = 0; mi < 2; mi++){
                    mma16816(C[mi][nf], AH[mi], bh0, bh1);
                    mma16816(C[mi][nf], AH[mi], bl0, bl1);
                    mma16816(C[mi][nf], AL[mi], bh0, bh1);
                }
            }
        }

        const float* bias = (p==0)?bq:(p==1)?bk:(p==2)?bv:bg;
        float* dst = (p==0)?g_q:(p==1)?g_k:(p==2)?g_v:g_gate;
        #pragma unroll
        for (int mi = 0; mi < 2; mi++){
            #pragma unroll
            for (int nf = 0; nf < 4; nf++){
                int col = n0 + nf*8 + 2*tig;
                float b0 = bias[col], b1 = bias[col+1];
                int r0 = row0 + m0 + mi*16 + gid;
                float v00 = C[mi][nf][0] + b0, v01 = C[mi][nf][1] + b1;
                float v10 = C[mi][nf][2] + b0, v11 = C[mi][nf][3] + b1;
                if (p == 3){
                    v00 = 1.f/(1.f+__expf(-v00)); v01 = 1.f/(1.f+__expf(-v01));
                    v10 = 1.f/(1.f+__expf(-v10)); v11 = 1.f/(1.f+__expf(-v11));
                }
                *(float2*)(dst + (size_t)r0*DD + col)     = make_float2(v00, v01);
                *(float2*)(dst + (size_t)(r0+8)*DD + col) = make_float2(v10, v11);
            }
        }
        __syncthreads();
    }
}

// ---------------- kernel 2: attention per (i,h), tensor-core flash ----------------
// 256 threads, warp owns 32 query rows. smem layout (uint32 units):
#define AQH 0
#define AQL 5120
#define AKH 10240
#define AKL 15360
#define AVH 20480
#define AVL 24704
#define APH 28928
#define APL 38144
#define ATOT 47360
__global__ __launch_bounds__(256,1) void k_attn()
{
    extern __shared__ uint32_t sm[];
    uint32_t* QH = sm + AQH;  uint32_t* QL = sm + AQL;   // [256][20]
    uint32_t* KH = sm + AKH;  uint32_t* KL = sm + AKL;   // [256][20]
    uint32_t* VTH = sm + AVH; uint32_t* VTL = sm + AVL;  // [32][132]
    __nv_bfloat16* VTHh = (__nv_bfloat16*)VTH;
    __nv_bfloat16* VTLh = (__nv_bfloat16*)VTL;

    const int i = blockIdx.x, h = blockIdx.y;
    const int tid = threadIdx.x;
    const int lane = tid & 31, wid = tid >> 5;
    const int gid = lane >> 2, tig = lane & 3;
    const size_t base = (size_t)i*LL*DD + h*DHEAD;
    const float scale = 0.17677669529663687f;

    // stage q (pre-scaled), k, v^T as bf16 hi/lo
    for (int idx = tid; idx < 2048; idx += 256){
        int r = idx >> 3, c4 = idx & 7;
        int d0 = c4*4;
        size_t g = base + (size_t)r*DD + d0;
        float4 qv = *(const float4*)(g_q + g);
        float4 kv = *(const float4*)(g_k + g);
        float4 vv = *(const float4*)(g_v + g);
        uint32_t hi, lo;
        split2(qv.x*scale, qv.y*scale, hi, lo); QH[r*20 + (d0>>1)] = hi; QL[r*20 + (d0>>1)] = lo;
        split2(qv.z*scale, qv.w*scale, hi, lo); QH[r*20 + (d0>>1)+1] = hi; QL[r*20 + (d0>>1)+1] = lo;
        split2(kv.x, kv.y, hi, lo); KH[r*20 + (d0>>1)] = hi; KL[r*20 + (d0>>1)] = lo;
        split2(kv.z, kv.w, hi, lo); KH[r*20 + (d0>>1)+1] = hi; KL[r*20 + (d0>>1)+1] = lo;
        float vf[4] = {vv.x, vv.y, vv.z, vv.w};
        #pragma unroll
        for (int e = 0; e < 4; e++){
            __nv_bfloat16 hh, ll; split1(vf[e], hh, ll);
            VTHh[(d0+e)*264 + r] = hh;
            VTLh[(d0+e)*264 + r] = ll;
        }
    }
    __syncthreads();

    uint32_t* PHW = sm + APH + wid*1152;   // [32][36]
    uint32_t* PLW = sm + APL + wid*1152;
    const int wrow = wid*32;

    float mrow[2][2], lrow[2][2], O[2][4][4];
    #pragma unroll
    for (int mi=0; mi<2; mi++)
        #pragma unroll
        for (int rr=0; rr<2; rr++){ mrow[mi][rr] = -1e30f; lrow[mi][rr] = 0.f; }
    #pragma unroll
    for (int mi=0; mi<2; mi++)
        #pragma unroll
        for (int nf=0; nf<4; nf++)
            #pragma unroll
            for (int q=0; q<4; q++) O[mi][nf][q] = 0.f;

    for (int ch = 0; ch < 4; ch++){
        float S[2][8][4];
        #pragma unroll
        for (int mi=0; mi<2; mi++)
            #pragma unroll
            for (int nf=0; nf<8; nf++)
                #pragma unroll
                for (int q=0; q<4; q++) S[mi][nf][q] = 0.f;

        // S = Q K^T (3-term split)
        #pragma unroll
        for (int ks = 0; ks < 2; ks++){
            uint32_t AH[2][4], AL[2][4];
            #pragma unroll
            for (int mi = 0; mi < 2; mi++){
                int r = wrow + mi*16 + gid;
                AH[mi][0] = QH[r*20 + ks*8 + tig];
                AH[mi][1] = QH[(r+8)*20 + ks*8 + tig];
                AH[mi][2] = QH[r*20 + ks*8 + tig + 4];
                AH[mi][3] = QH[(r+8)*20 + ks*8 + tig + 4];
                AL[mi][0] = QL[r*20 + ks*8 + tig];
                AL[mi][1] = QL[(r+8)*20 + ks*8 + tig];
                AL[mi][2] = QL[r*20 + ks*8 + tig + 4];
                AL[mi][3] = QL[(r+8)*20 + ks*8 + tig + 4];
            }
            #pragma unroll
            for (int nf = 0; nf < 8; nf++){
                int key = ch*64 + nf*8 + gid;
                uint32_t bh0 = KH[key*20 + ks*8 + tig];
                uint32_t bh1 = KH[key*20 + ks*8 + tig + 4];
                uint32_t bl0 = KL[key*20 + ks*8 + tig];
                uint32_t bl1 = KL[key*20 + ks*8 + tig + 4];
                #pragma unroll
                for (int mi = 0; mi < 2; mi++){
                    mma16816(S[mi][nf], AH[mi], bh0, bh1);
                    mma16816(S[mi][nf], AH[mi], bl0, bl1);
                    mma16816(S[mi][nf], AL[mi], bh0, bh1);
                }
            }
        }

        // mask + online softmax update
        #pragma unroll
        for (int mi = 0; mi < 2; mi++){
            #pragma unroll
            for (int rr = 0; rr < 2; rr++){
                int row = wrow + mi*16 + gid + rr*8;
                unsigned w0 = g_mask[row*8 + ch*2];
                unsigned w1 = g_mask[row*8 + ch*2 + 1];
                float rmax = -1e30f;
                #pragma unroll
                for (int nf = 0; nf < 8; nf++){
                    #pragma unroll
                    for (int cc = 0; cc < 2; cc++){
                        int kb = nf*8 + 2*tig + cc;
                        unsigned w = (kb < 32) ? w0 : w1;
                        float s = S[mi][nf][rr*2+cc];
                        if (!((w >> (kb & 31)) & 1u)) s = -1e9f;
                        S[mi][nf][rr*2+cc] = s;
                        rmax = fmaxf(rmax, s);
                    }
                }
                rmax = fmaxf(rmax, __shfl_xor_sync(0xffffffffu, rmax, 1));
                rmax = fmaxf(rmax, __shfl_xor_sync(0xffffffffu, rmax, 2));
                float mnew = fmaxf(mrow[mi][rr], rmax);
                float corr = __expf(mrow[mi][rr] - mnew);
                mrow[mi][rr] = mnew;
                lrow[mi][rr] *= corr;
                #pragma unroll
                for (int nf = 0; nf < 4; nf++){
                    O[mi][nf][rr*2]   *= corr;
                    O[mi][nf][rr*2+1] *= corr;
                }
                float ls = 0.f;
                #pragma unroll
                for (int nf = 0; nf < 8; nf++){
                    float p0 = __expf(S[mi][nf][rr*2]   - mnew);
                    float p1 = __expf(S[mi][nf][rr*2+1] - mnew);
                    S[mi][nf][rr*2] = p0; S[mi][nf][rr*2+1] = p1;
                    ls += p0 + p1;
                }
                lrow[mi][rr] += ls;
                // store P (bf16 split, packed key pairs)
                int rw = mi*16 + gid + rr*8;
                #pragma unroll
                for (int nf = 0; nf < 8; nf++){
                    uint32_t hi, lo;
                    split2(S[mi][nf][rr*2], S[mi][nf][rr*2+1], hi, lo);
                    PHW[rw*36 + nf*4 + tig] = hi;
                    PLW[rw*36 + nf*4 + tig] = lo;
                }
            }
        }
        __syncwarp();

        // O += P V (3-term split)
        #pragma unroll
        for (int ks = 0; ks < 4; ks++){
            uint32_t AH[2][4], AL[2][4];
            #pragma unroll
            for (int mi = 0; mi < 2; mi++){
                int r = mi*16 + gid;
                AH[mi][0] = PHW[r*36 + ks*8 + tig];
                AH[mi][1] = PHW[(r+8)*36 + ks*8 + tig];
                AH[mi][2] = PHW[r*36 + ks*8 + tig + 4];
                AH[mi][3] = PHW[(r+8)*36 + ks*8 + tig + 4];
                AL[mi][0] = PLW[r*36 + ks*8 + tig];
                AL[mi][1] = PLW[(r+8)*36 + ks*8 + tig];
                AL[mi][2] = PLW[r*36 + ks*8 + tig + 4];
                AL[mi][3] = PLW[(r+8)*36 + ks*8 + tig + 4];
            }
            #pragma unroll
            for (int nf = 0; nf < 4; nf++){
                int dim = nf*8 + gid;
                uint32_t bh0 = VTH[dim*132 + ch*32 + ks*8 + tig];
                uint32_t bh1 = VTH[dim*132 + ch*32 + ks*8 + tig + 4];
                uint32_t bl0 = VTL[dim*132 + ch*32 + ks*8 + tig];
                uint32_t bl1 = VTL[dim*132 + ch*32 + ks*8 + tig + 4];
                #pragma unroll
                for (int mi = 0; mi < 2; mi++){
                    mma16816(O[mi][nf], AH[mi], bh0, bh1);
                    mma16816(O[mi][nf], AH[mi], bl0, bl1);
                    mma16816(O[mi][nf], AL[mi], bh0, bh1);
                }
            }
        }
        __syncwarp();
    }

    // finalize + write
    #pragma unroll
    for (int mi = 0; mi < 2; mi++){
        #pragma unroll
        for (int rr = 0; rr < 2; rr++){
            float l = lrow[mi][rr];
            l += __shfl_xor_sync(0xffffffffu, l, 1);
            l += __shfl_xor_sync(0xffffffffu, l, 2);
            float inv = 1.f / l;
            int row = wrow + mi*16 + gid + rr*8;
            #pragma unroll
            for (int nf = 0; nf < 4; nf++){
                float o0 = O[mi][nf][rr*2]   * inv;
                float o1 = O[mi][nf][rr*2+1] * inv;
                *(float2*)(g_att + base + (size_t)row*DD + nf*8 + 2*tig) = make_float2(o0, o1);
            }
        }
    }
}

// ---------------- kernel 3: out projection + gate (tensor) ----------------
__global__ __launch_bounds__(256,2) void k_outproj(const float* __restrict__ bo,
                                                   float* __restrict__ out)
{
    extern __shared__ uint32_t sm[];
    uint32_t* AHs = sm;
    uint32_t* ALs = sm + 64*WST;
    uint32_t* WH  = sm + 2*64*WST;
    uint32_t* WL  = WH + 128*WST;

    const int row0 = blockIdx.x * 64;
    const int tid = threadIdx.x;
    const int lane = tid & 31, wid = tid >> 5;
    const int gid = lane >> 2, tig = lane & 3;

    // stage activations (split)
    for (int idx = tid; idx < 2048; idx += 256){
        int r = idx >> 5, c4 = idx & 31;
        int d0 = c4*4;
        float4 a = *(const float4*)(g_att + (size_t)(row0+r)*DD + d0);
        uint32_t hi, lo;
        split2(a.x, a.y, hi, lo); AHs[r*WST + (d0>>1)]   = hi; ALs[r*WST + (d0>>1)]   = lo;
        split2(a.z, a.w, hi, lo); AHs[r*WST + (d0>>1)+1] = hi; ALs[r*WST + (d0>>1)+1] = lo;
    }
    // stage Wo (index 4)
    {
        const float4* sH = (const float4*)(g_WbH + 4*128*WST);
        const float4* sL = (const float4*)(g_WbL + 4*128*WST);
        float4* dH = (float4*)WH; float4* dL = (float4*)WL;
        for (int idx = tid; idx < 128*WST/4; idx += 256){ dH[idx] = sH[idx]; dL[idx] = sL[idx]; }
    }
    __syncthreads();

    const int wm = wid >> 2, wn = wid & 3;
    const int m0 = wm*32, n0 = wn*32;

    float C[2][4][4];
    #pragma unroll
    for (int mi=0; mi<2; mi++)
        #pragma unroll
        for (int nf=0; nf<4; nf++)
            #pragma unroll
            for (int q=0; q<4; q++) C[mi][nf][q] = 0.f;

    #pragma unroll
    for (int ks = 0; ks < 8; ks++){
        uint32_t AH[2][4], AL[2][4];
        #pragma unroll
        for (int mi = 0; mi < 2; mi++){
            int r = m0 + mi*16 + gid;
            AH[mi][0] = AHs[r*WST + ks*8 + tig];
            AH[mi][1] = AHs[(r+8)*WST + ks*8 + tig];
            AH[mi][2] = AHs[r*WST + ks*8 + tig + 4];
            AH[mi][3] = AHs[(r+8)*WST + ks*8 + tig + 4];
            AL[mi][0] = ALs[r*WST + ks*8 + tig];
            AL[mi][1] = ALs[(r+8)*WST + ks*8 + tig];
            AL[mi][2] = ALs[r*WST + ks*8 + tig + 4];
            AL[mi][3] = ALs[(r+8)*WST + ks*8 + tig + 4];
        }
        #pragma unroll
        for (int nf = 0; nf < 4; nf++){
            int e = n0 + nf*8 + gid;
            uint32_t bh0 = WH[e*WST + ks*8 + tig];
            uint32_t bh1 = WH[e*WST + ks*8 + tig + 4];
            uint32_t bl0 = WL[e*WST + ks*8 + tig];
            uint32_t bl1 = WL[e*WST + ks*8 + tig + 4];
            #pragma unroll
            for (int mi = 0; mi < 2; mi++){
                mma16816(C[mi][nf], AH[mi], bh0, bh1);
                mma16816(C[mi][nf], AH[mi], bl0, bl1);
                mma16816(C[mi][nf], AL[mi], bh0, bh1);
            }
        }
    }

    #pragma unroll
    for (int mi = 0; mi < 2; mi++){
        #pragma unroll
        for (int nf = 0; nf < 4; nf++){
            int col = n0 + nf*8 + 2*tig;
            float b0 = bo[col], b1 = bo[col+1];
            int r0 = row0 + m0 + mi*16 + gid;
            size_t a0 = (size_t)r0*DD + col;
            size_t a1 = (size_t)(r0+8)*DD + col;
            float2 gt0 = *(const float2*)(g_gate + a0);
            float2 gt1 = *(const float2*)(g_gate + a1);
            *(float2*)(out + a0) = make_float2((C[mi][nf][0]+b0)*gt0.x, (C[mi][nf][1]+b1)*gt0.y);
            *(float2*)(out + a1) = make_float2((C[mi][nf][2]+b0)*gt1.x, (C[mi][nf][3]+b1)*gt1.y);
        }
    }
}

// ---------------- launch ----------------
extern "C" void kernel_launch(void* const* d_in, const int* in_sizes, int n_in,
                              void* d_out, int out_size)
{
    const float* pair = (const float*)d_in[0];
    const int*   mask = (const int*)d_in[1];
    const float* ln_g = (const float*)d_in[2];
    const float* ln_b = (const float*)d_in[3];
    const float* Wq = (const float*)d_in[4];  const float* bq = (const float*)d_in[5];
    const float* Wk = (const float*)d_in[6];  const float* bk = (const float*)d_in[7];
    const float* Wv = (const float*)d_in[8];  const float* bv = (const float*)d_in[9];
    const float* Wo = (const float*)d_in[10]; const float* bo = (const float*)d_in[11];
    const float* Wg = (const float*)d_in[12]; const float* bg = (const float*)d_in[13];
    float* out = (float*)d_out;

    const int smemP = (2*64*WST + 2*128*WST) * 4;   // 104448
    const int smemA = ATOT * 4;                      // 189440
    cudaFuncSetAttribute(k_lnproj,  cudaFuncAttributeMaxDynamicSharedMemorySize, smemP);
    cudaFuncSetAttribute(k_outproj, cudaFuncAttributeMaxDynamicSharedMemorySize, smemP);
    cudaFuncSetAttribute(k_attn,    cudaFuncAttributeMaxDynamicSharedMemorySize, smemA);

    k_prep<<<5, 256>>>(Wq, Wk, Wv, Wg, Wo);
    k_maskpack<<<1, 256>>>(mask);
    k_lnproj<<<NROWS/64, 256, smemP>>>(pair, ln_g, ln_b, bq, bk, bv, bg);
    dim3 ga(LL, NHEAD);
    k_attn<<<ga, 256, smemA>>>();
    k_outproj<<<NROWS/64, 256, smemP>>>(bo, out);
}

// round 5
// speedup vs baseline: 2.4502x; 1.1440x over previous
#include <cuda_runtime.h>
#include <cuda_bf16.h>
#include <cstdint>
#include <math.h>

#define LL 256
#define DD 128
#define NHEAD 4
#define DHEAD 32
#define NROWS (LL*LL)   // 65536
#define WST 68          // packed-pair row stride (uint32) for 128-wide matrices

// ---------------- scratch ----------------
__device__ uint32_t g_WbH[5*128*WST];   // bf16-hi packed pairs, rows=e, pairs along d
__device__ uint32_t g_WbL[5*128*WST];   // bf16-lo
__device__ float g_q[(size_t)NROWS*DD];
__device__ float g_k[(size_t)NROWS*DD];
__device__ float g_v[(size_t)NROWS*DD];
__device__ float g_gate[(size_t)NROWS*DD];
__device__ float g_att[(size_t)NROWS*DD];
__device__ unsigned g_mask[LL*8];

// ---------------- helpers ----------------
__device__ __forceinline__ uint32_t pack_bf16(__nv_bfloat16 a, __nv_bfloat16 b){
    __nv_bfloat162 t; t.x = a; t.y = b;
    return *reinterpret_cast<uint32_t*>(&t);
}
__device__ __forceinline__ void split2(float x0, float x1, uint32_t& hi, uint32_t& lo){
    __nv_bfloat16 h0 = __float2bfloat16(x0);
    __nv_bfloat16 h1 = __float2bfloat16(x1);
    __nv_bfloat16 l0 = __float2bfloat16(x0 - __bfloat162float(h0));
    __nv_bfloat16 l1 = __float2bfloat16(x1 - __bfloat162float(h1));
    hi = pack_bf16(h0, h1); lo = pack_bf16(l0, l1);
}
__device__ __forceinline__ void split1(float x, __nv_bfloat16& h, __nv_bfloat16& l){
    h = __float2bfloat16(x);
    l = __float2bfloat16(x - __bfloat162float(h));
}
__device__ __forceinline__ void mma16816(float* c, const uint32_t* a, uint32_t b0, uint32_t b1){
    asm volatile("mma.sync.aligned.m16n8k16.row.col.f32.bf16.bf16.f32 "
        "{%0,%1,%2,%3}, {%4,%5,%6,%7}, {%8,%9}, {%0,%1,%2,%3};\n"
        : "+f"(c[0]), "+f"(c[1]), "+f"(c[2]), "+f"(c[3])
        : "r"(a[0]), "r"(a[1]), "r"(a[2]), "r"(a[3]), "r"(b0), "r"(b1));
}

// ---------------- kernel: prep weights (split + pack pairs along d) ----------------
__global__ void k_prep(const float* __restrict__ Wq, const float* __restrict__ Wk,
                       const float* __restrict__ Wv, const float* __restrict__ Wg,
                       const float* __restrict__ Wo)
{
    int m = blockIdx.x;
    const float* W = (m==0)?Wq:(m==1)?Wk:(m==2)?Wv:(m==3)?Wg:Wo;
    uint32_t* H = g_WbH + m*128*WST;
    uint32_t* L = g_WbL + m*128*WST;
    for (int idx = threadIdx.x; idx < 128*WST; idx += blockDim.x){
        int e = idx / WST, p = idx % WST;
        uint32_t hv = 0, lv = 0;
        if (p < 64){
            float x0 = W[e*DD + 2*p], x1 = W[e*DD + 2*p + 1];
            split2(x0, x1, hv, lv);
        }
        H[idx] = hv; L[idx] = lv;
    }
}

// ---------------- kernel: pack mask ----------------
__global__ void k_maskpack(const int* __restrict__ mask)
{
    int j = threadIdx.x;
    const int* mrow = mask + (size_t)j*LL;
    #pragma unroll
    for (int w = 0; w < 8; w++){
        unsigned bits = 0;
        #pragma unroll
        for (int b = 0; b < 32; b++) bits |= (mrow[w*32+b] != 0 ? 1u : 0u) << b;
        g_mask[j*8 + w] = bits;
    }
}

// ---------------- kernel 1: LayerNorm + q/k/v/gate projections (tensor) ----------------
// 256 threads, 64 rows/block. smem: PN hi/lo [64][68] + W hi/lo [128][68] = 104.4KB
__global__ __launch_bounds__(256,2) void k_lnproj(
    const float* __restrict__ pair,
    const float* __restrict__ ln_g, const float* __restrict__ ln_b,
    const float* __restrict__ bq, const float* __restrict__ bk,
    const float* __restrict__ bv, const float* __restrict__ bg)
{
    extern __shared__ uint32_t sm[];
    uint32_t* PNH = sm;                 // 64*68
    uint32_t* PNL = sm + 64*WST;
    uint32_t* WH  = sm + 2*64*WST;      // 128*68
    uint32_t* WL  = WH + 128*WST;
    __nv_bfloat16* PNHh = (__nv_bfloat16*)PNH;
    __nv_bfloat16* PNLh = (__nv_bfloat16*)PNL;

    const int row0 = blockIdx.x * 64;
    const int tid = threadIdx.x;
    const int lane = tid & 31, wid = tid >> 5;
    const int gid = lane >> 2, tig = lane & 3;

    // ---- LayerNorm: 8 warps x 8 rows, split to bf16 hi/lo in smem ----
    float lg[4], lb[4];
    #pragma unroll
    for (int t = 0; t < 4; t++){ lg[t] = ln_g[lane + 32*t]; lb[t] = ln_b[lane + 32*t]; }
    for (int rr = 0; rr < 8; rr++){
        int r = wid*8 + rr;
        const float* x = pair + (size_t)(row0 + r)*DD;
        float v[4];
        #pragma unroll
        for (int t = 0; t < 4; t++) v[t] = x[lane + 32*t];
        float s = v[0]+v[1]+v[2]+v[3];
        #pragma unroll
        for (int o = 16; o > 0; o >>= 1) s += __shfl_xor_sync(0xffffffffu, s, o);
        float mu = s * (1.f/128.f);
        float sq = 0.f;
        #pragma unroll
        for (int t = 0; t < 4; t++){ v[t] -= mu; sq += v[t]*v[t]; }
        #pragma unroll
        for (int o = 16; o > 0; o >>= 1) sq += __shfl_xor_sync(0xffffffffu, sq, o);
        float rstd = rsqrtf(sq*(1.f/128.f) + 1e-5f);
        #pragma unroll
        for (int t = 0; t < 4; t++){
            float pn = v[t]*rstd*lg[t] + lb[t];
            __nv_bfloat16 h, l; split1(pn, h, l);
            PNHh[r*(2*WST) + lane + 32*t] = h;
            PNLh[r*(2*WST) + lane + 32*t] = l;
        }
    }
    __syncthreads();

    const int wm = wid >> 2, wn = wid & 3;
    const int m0 = wm*32, n0 = wn*32;

    for (int p = 0; p < 4; p++){
        // stage weights
        const float4* sH = (const float4*)(g_WbH + p*128*WST);
        const float4* sL = (const float4*)(g_WbL + p*128*WST);
        float4* dH = (float4*)WH; float4* dL = (float4*)WL;
        for (int idx = tid; idx < 128*WST/4; idx += 256){ dH[idx] = sH[idx]; dL[idx] = sL[idx]; }
        __syncthreads();

        float C[2][4][4];
        #pragma unroll
        for (int mi=0; mi<2; mi++)
            #pragma unroll
            for (int nf=0; nf<4; nf++)
                #pragma unroll
                for (int q=0; q<4; q++) C[mi][nf][q] = 0.f;

        #pragma unroll
        for (int ks = 0; ks < 8; ks++){
            uint32_t AH[2][4], AL[2][4];
            #pragma unroll
            for (int mi = 0; mi < 2; mi++){
                int r = m0 + mi*16 + gid;
                AH[mi][0] = PNH[r*WST + ks*8 + tig];
                AH[mi][1] = PNH[(r+8)*WST + ks*8 + tig];
                AH[mi][2] = PNH[r*WST + ks*8 + tig + 4];
                AH[mi][3] = PNH[(r+8)*WST + ks*8 + tig + 4];
                AL[mi][0] = PNL[r*WST + ks*8 + tig];
                AL[mi][1] = PNL[(r+8)*WST + ks*8 + tig];
                AL[mi][2] = PNL[r*WST + ks*8 + tig + 4];
                AL[mi][3] = PNL[(r+8)*WST + ks*8 + tig + 4];
            }
            #pragma unroll
            for (int nf = 0; nf < 4; nf++){
                int e = n0 + nf*8 + gid;
                uint32_t bh0 = WH[e*WST + ks*8 + tig];
                uint32_t bh1 = WH[e*WST + ks*8 + tig + 4];
                uint32_t bl0 = WL[e*WST + ks*8 + tig];
                uint32_t bl1 = WL[e*WST + ks*8 + tig + 4];
                #pragma unroll
                for (int mi = 0; mi < 2; mi++){
                    mma16816(C[mi][nf], AH[mi], bh0, bh1);
                    mma16816(C[mi][nf], AH[mi], bl0, bl1);
                    mma16816(C[mi][nf], AL[mi], bh0, bh1);
                }
            }
        }

        const float* bias = (p==0)?bq:(p==1)?bk:(p==2)?bv:bg;
        float* dst = (p==0)?g_q:(p==1)?g_k:(p==2)?g_v:g_gate;
        #pragma unroll
        for (int mi = 0; mi < 2; mi++){
            #pragma unroll
            for (int nf = 0; nf < 4; nf++){
                int col = n0 + nf*8 + 2*tig;
                float b0 = bias[col], b1 = bias[col+1];
                int r0 = row0 + m0 + mi*16 + gid;
                float v00 = C[mi][nf][0] + b0, v01 = C[mi][nf][1] + b1;
                float v10 = C[mi][nf][2] + b0, v11 = C[mi][nf][3] + b1;
                if (p == 3){
                    v00 = 1.f/(1.f+__expf(-v00)); v01 = 1.f/(1.f+__expf(-v01));
                    v10 = 1.f/(1.f+__expf(-v10)); v11 = 1.f/(1.f+__expf(-v11));
                }
                *(float2*)(dst + (size_t)r0*DD + col)     = make_float2(v00, v01);
                *(float2*)(dst + (size_t)(r0+8)*DD + col) = make_float2(v10, v11);
            }
        }
        __syncthreads();
    }
}

// ---------------- kernel 2: attention per (i,h,half), tensor-core flash ----------------
// 256 threads / 8 warps, each warp owns 16 query rows. 2 blocks per (i,h).
// P and Q live in registers (C-fragment == A-fragment layout reuse).
// smem (uint32): KH[256][20], KL[256][20], VTH[32][132], VTL[32][132] = 74.75KB
#define AKH 0
#define AKL 5120
#define AVH 10240
#define AVL 14464
#define ATOT 18688
__global__ __launch_bounds__(256,2) void k_attn()
{
    extern __shared__ uint32_t sm[];
    uint32_t* KH = sm + AKH;  uint32_t* KL = sm + AKL;   // [256][20]
    uint32_t* VTH = sm + AVH; uint32_t* VTL = sm + AVL;  // [32][132]
    __nv_bfloat16* VTHh = (__nv_bfloat16*)VTH;
    __nv_bfloat16* VTLh = (__nv_bfloat16*)VTL;

    const int i = blockIdx.x, h = blockIdx.y, half = blockIdx.z;
    const int tid = threadIdx.x;
    const int lane = tid & 31, wid = tid >> 5;
    const int gid = lane >> 2, tig = lane & 3;
    const size_t base = (size_t)i*LL*DD + h*DHEAD;
    const float scale = 0.17677669529663687f;   // 1/sqrt(32)

    // stage K, V^T as bf16 hi/lo
    for (int idx = tid; idx < 2048; idx += 256){  // 256 rows * 8 float4
        int r = idx >> 3, c4 = idx & 7;
        int d0 = c4*4;
        size_t g = base + (size_t)r*DD + d0;
        float4 kv = *(const float4*)(g_k + g);
        float4 vv = *(const float4*)(g_v + g);
        uint32_t hi, lo;
        split2(kv.x, kv.y, hi, lo); KH[r*20 + (d0>>1)]   = hi; KL[r*20 + (d0>>1)]   = lo;
        split2(kv.z, kv.w, hi, lo); KH[r*20 + (d0>>1)+1] = hi; KL[r*20 + (d0>>1)+1] = lo;
        float vf[4] = {vv.x, vv.y, vv.z, vv.w};
        #pragma unroll
        for (int e = 0; e < 4; e++){
            __nv_bfloat16 hh, ll; split1(vf[e], hh, ll);
            VTHh[(d0+e)*264 + r] = hh;
            VTLh[(d0+e)*264 + r] = ll;
        }
    }

    // Q fragments directly from gmem (this warp's 16 rows), pre-scaled
    const int j0 = half*128 + wid*16 + gid;      // local query row (fragment row gid)
    uint32_t QHf[2][4], QLf[2][4];
    {
        const float* q0 = g_q + base + (size_t)j0*DD;
        const float* q1 = q0 + 8*DD;
        #pragma unroll
        for (int ks = 0; ks < 2; ks++){
            int d = ks*16 + 2*tig;
            float2 a0 = *(const float2*)(q0 + d);
            float2 a1 = *(const float2*)(q1 + d);
            float2 a2 = *(const float2*)(q0 + d + 8);
            float2 a3 = *(const float2*)(q1 + d + 8);
            split2(a0.x*scale, a0.y*scale, QHf[ks][0], QLf[ks][0]);
            split2(a1.x*scale, a1.y*scale, QHf[ks][1], QLf[ks][1]);
            split2(a2.x*scale, a2.y*scale, QHf[ks][2], QLf[ks][2]);
            split2(a3.x*scale, a3.y*scale, QHf[ks][3], QLf[ks][3]);
        }
    }
    __syncthreads();

    float mrow[2], lrow[2], O[4][4];
    #pragma unroll
    for (int rr = 0; rr < 2; rr++){ mrow[rr] = -1e30f; lrow[rr] = 0.f; }
    #pragma unroll
    for (int nf = 0; nf < 4; nf++)
        #pragma unroll
        for (int q = 0; q < 4; q++) O[nf][q] = 0.f;

    for (int ch = 0; ch < 4; ch++){
        float S[8][4];
        #pragma unroll
        for (int nf = 0; nf < 8; nf++)
            #pragma unroll
            for (int q = 0; q < 4; q++) S[nf][q] = 0.f;

        // S = Q K^T (3-term split)
        #pragma unroll
        for (int ks = 0; ks < 2; ks++){
            #pragma unroll
            for (int nf = 0; nf < 8; nf++){
                int key = ch*64 + nf*8 + gid;
                uint32_t bh0 = KH[key*20 + ks*8 + tig];
                uint32_t bh1 = KH[key*20 + ks*8 + tig + 4];
                uint32_t bl0 = KL[key*20 + ks*8 + tig];
                uint32_t bl1 = KL[key*20 + ks*8 + tig + 4];
                mma16816(S[nf], QHf[ks], bh0, bh1);
                mma16816(S[nf], QHf[ks], bl0, bl1);
                mma16816(S[nf], QLf[ks], bh0, bh1);
            }
        }

        // mask + online softmax
        #pragma unroll
        for (int rr = 0; rr < 2; rr++){
            int j = j0 + rr*8;
            unsigned w0 = g_mask[j*8 + ch*2];
            unsigned w1 = g_mask[j*8 + ch*2 + 1];
            float rmax = -1e30f;
            #pragma unroll
            for (int nf = 0; nf < 8; nf++){
                #pragma unroll
                for (int cc = 0; cc < 2; cc++){
                    int kb = nf*8 + 2*tig + cc;
                    unsigned w = (kb < 32) ? w0 : w1;
                    float s = S[nf][rr*2+cc];
                    if (!((w >> (kb & 31)) & 1u)) s = -1e9f;
                    S[nf][rr*2+cc] = s;
                    rmax = fmaxf(rmax, s);
                }
            }
            rmax = fmaxf(rmax, __shfl_xor_sync(0xffffffffu, rmax, 1));
            rmax = fmaxf(rmax, __shfl_xor_sync(0xffffffffu, rmax, 2));
            float mnew = fmaxf(mrow[rr], rmax);
            float corr = __expf(mrow[rr] - mnew);
            mrow[rr] = mnew;
            lrow[rr] *= corr;
            #pragma unroll
            for (int nf = 0; nf < 4; nf++){
                O[nf][rr*2]   *= corr;
                O[nf][rr*2+1] *= corr;
            }
            float ls = 0.f;
            #pragma unroll
            for (int nf = 0; nf < 8; nf++){
                float p0 = __expf(S[nf][rr*2]   - mnew);
                float p1 = __expf(S[nf][rr*2+1] - mnew);
                S[nf][rr*2] = p0; S[nf][rr*2+1] = p1;
                ls += p0 + p1;
            }
            lrow[rr] += ls;
        }

        // O += P V  (P built from S fragments in registers: C-frag == A-frag)
        #pragma unroll
        for (int g = 0; g < 4; g++){   // 16-key groups within the 64-key chunk
            uint32_t AH[4], AL[4];
            split2(S[2*g][0],   S[2*g][1],   AH[0], AL[0]);   // row gid,   k=2tig,2tig+1
            split2(S[2*g][2],   S[2*g][3],   AH[1], AL[1]);   // row gid+8, k=2tig,2tig+1
            split2(S[2*g+1][0], S[2*g+1][1], AH[2], AL[2]);   // row gid,   k=2tig+8
            split2(S[2*g+1][2], S[2*g+1][3], AH[3], AL[3]);   // row gid+8, k=2tig+8
            #pragma unroll
            for (int nf = 0; nf < 4; nf++){
                int dim = nf*8 + gid;
                uint32_t bh0 = VTH[dim*132 + ch*32 + g*8 + tig];
                uint32_t bh1 = VTH[dim*132 + ch*32 + g*8 + tig + 4];
                uint32_t bl0 = VTL[dim*132 + ch*32 + g*8 + tig];
                uint32_t bl1 = VTL[dim*132 + ch*32 + g*8 + tig + 4];
                mma16816(O[nf], AH, bh0, bh1);
                mma16816(O[nf], AH, bl0, bl1);
                mma16816(O[nf], AL, bh0, bh1);
            }
        }
    }

    // finalize + write
    #pragma unroll
    for (int rr = 0; rr < 2; rr++){
        float l = lrow[rr];
        l += __shfl_xor_sync(0xffffffffu, l, 1);
        l += __shfl_xor_sync(0xffffffffu, l, 2);
        float inv = 1.f / l;
        int j = j0 + rr*8;
        #pragma unroll
        for (int nf = 0; nf < 4; nf++){
            float o0 = O[nf][rr*2]   * inv;
            float o1 = O[nf][rr*2+1] * inv;
            *(float2*)(g_att + base + (size_t)j*DD + nf*8 + 2*tig) = make_float2(o0, o1);
        }
    }
}

// ---------------- kernel 3: out projection + gate (tensor) ----------------
__global__ __launch_bounds__(256,2) void k_outproj(const float* __restrict__ bo,
                                                   float* __restrict__ out)
{
    extern __shared__ uint32_t sm[];
    uint32_t* AHs = sm;
    uint32_t* ALs = sm + 64*WST;
    uint32_t* WH  = sm + 2*64*WST;
    uint32_t* WL  = WH + 128*WST;

    const int row0 = blockIdx.x * 64;
    const int tid = threadIdx.x;
    const int lane = tid & 31, wid = tid >> 5;
    const int gid = lane >> 2, tig = lane & 3;

    // stage activations (split)
    for (int idx = tid; idx < 2048; idx += 256){
        int r = idx >> 5, c4 = idx & 31;
        int d0 = c4*4;
        float4 a = *(const float4*)(g_att + (size_t)(row0+r)*DD + d0);
        uint32_t hi, lo;
        split2(a.x, a.y, hi, lo); AHs[r*WST + (d0>>1)]   = hi; ALs[r*WST + (d0>>1)]   = lo;
        split2(a.z, a.w, hi, lo); AHs[r*WST + (d0>>1)+1] = hi; ALs[r*WST + (d0>>1)+1] = lo;
    }
    // stage Wo (index 4)
    {
        const float4* sH = (const float4*)(g_WbH + 4*128*WST);
        const float4* sL = (const float4*)(g_WbL + 4*128*WST);
        float4* dH = (float4*)WH; float4* dL = (float4*)WL;
        for (int idx = tid; idx < 128*WST/4; idx += 256){ dH[idx] = sH[idx]; dL[idx] = sL[idx]; }
    }
    __syncthreads();

    const int wm = wid >> 2, wn = wid & 3;
    const int m0 = wm*32, n0 = wn*32;

    float C[2][4][4];
    #pragma unroll
    for (int mi=0; mi<2; mi++)
        #pragma unroll
        for (int nf=0; nf<4; nf++)
            #pragma unroll
            for (int q=0; q<4; q++) C[mi][nf][q] = 0.f;

    #pragma unroll
    for (int ks = 0; ks < 8; ks++){
        uint32_t AH[2][4], AL[2][4];
        #pragma unroll
        for (int mi = 0; mi < 2; mi++){
            int r = m0 + mi*16 + gid;
            AH[mi][0] = AHs[r*WST + ks*8 + tig];
            AH[mi][1] = AHs[(r+8)*WST + ks*8 + tig];
            AH[mi][2] = AHs[r*WST + ks*8 + tig + 4];
            AH[mi][3] = AHs[(r+8)*WST + ks*8 + tig + 4];
            AL[mi][0] = ALs[r*WST + ks*8 + tig];
            AL[mi][1] = ALs[(r+8)*WST + ks*8 + tig];
            AL[mi][2] = ALs[r*WST + ks*8 + tig + 4];
            AL[mi][3] = ALs[(r+8)*WST + ks*8 + tig + 4];
        }
        #pragma unroll
        for (int nf = 0; nf < 4; nf++){
            int e = n0 + nf*8 + gid;
            uint32_t bh0 = WH[e*WST + ks*8 + tig];
            uint32_t bh1 = WH[e*WST + ks*8 + tig + 4];
            uint32_t bl0 = WL[e*WST + ks*8 + tig];
            uint32_t bl1 = WL[e*WST + ks*8 + tig + 4];
            #pragma unroll
            for (int mi = 0; mi < 2; mi++){
                mma16816(C[mi][nf], AH[mi], bh0, bh1);
                mma16816(C[mi][nf], AH[mi], bl0, bl1);
                mma16816(C[mi][nf], AL[mi], bh0, bh1);
            }
        }
    }

    #pragma unroll
    for (int mi = 0; mi < 2; mi++){
        #pragma unroll
        for (int nf = 0; nf < 4; nf++){
            int col = n0 + nf*8 + 2*tig;
            float b0 = bo[col], b1 = bo[col+1];
            int r0 = row0 + m0 + mi*16 + gid;
            size_t a0 = (size_t)r0*DD + col;
            size_t a1 = (size_t)(r0+8)*DD + col;
            float2 gt0 = *(const float2*)(g_gate + a0);
            float2 gt1 = *(const float2*)(g_gate + a1);
            *(float2*)(out + a0) = make_float2((C[mi][nf][0]+b0)*gt0.x, (C[mi][nf][1]+b1)*gt0.y);
            *(float2*)(out + a1) = make_float2((C[mi][nf][2]+b0)*gt1.x, (C[mi][nf][3]+b1)*gt1.y);
        }
    }
}

// ---------------- launch ----------------
extern "C" void kernel_launch(void* const* d_in, const int* in_sizes, int n_in,
                              void* d_out, int out_size)
{
    const float* pair = (const float*)d_in[0];
    const int*   mask = (const int*)d_in[1];
    const float* ln_g = (const float*)d_in[2];
    const float* ln_b = (const float*)d_in[3];
    const float* Wq = (const float*)d_in[4];  const float* bq = (const float*)d_in[5];
    const float* Wk = (const float*)d_in[6];  const float* bk = (const float*)d_in[7];
    const float* Wv = (const float*)d_in[8];  const float* bv = (const float*)d_in[9];
    const float* Wo = (const float*)d_in[10]; const float* bo = (const float*)d_in[11];
    const float* Wg = (const float*)d_in[12]; const float* bg = (const float*)d_in[13];
    float* out = (float*)d_out;

    const int smemP = (2*64*WST + 2*128*WST) * 4;   // 104448
    const int smemA = ATOT * 4;                      // 74752
    cudaFuncSetAttribute(k_lnproj,  cudaFuncAttributeMaxDynamicSharedMemorySize, smemP);
    cudaFuncSetAttribute(k_outproj, cudaFuncAttributeMaxDynamicSharedMemorySize, smemP);
    cudaFuncSetAttribute(k_attn,    cudaFuncAttributeMaxDynamicSharedMemorySize, smemA);

    k_prep<<<5, 256>>>(Wq, Wk, Wv, Wg, Wo);
    k_maskpack<<<1, 256>>>(mask);
    k_lnproj<<<NROWS/64, 256, smemP>>>(pair, ln_g, ln_b, bq, bk, bv, bg);
    dim3 ga(LL, NHEAD, 2);
    k_attn<<<ga, 256, smemA>>>();
    k_outproj<<<NROWS/64, 256, smemP>>>(bo, out);
}